// round 2
// baseline (speedup 1.0000x reference)
#include <cuda_runtime.h>

#define BB 8
#define HH 512
#define WW 512
#define NMASK 2
#define BIGF 1.0e6f
#define BIG2 1.0e12f
#define NPIX (BB * HH * WW)          // 2097152
#define NROWS (NMASK * BB * HH)      // 8192
#define NGRP  (NMASK * BB)           // 16

// Scratch: g^2 (vertical 1D dist squared) for both masks, per-row partials.
__device__ float        g_dtsq[NMASK * NPIX];      // 16 MB
__device__ double       g_rowsum[NROWS];           // unnormalized sum(d^2 * dt^2) per row
__device__ unsigned int g_maxbits[NGRP];           // per-(mask,batch) max dt^2 (float bits)

__device__ __forceinline__ bool is_fg(const float* __restrict__ out,
                                      const int* __restrict__ tgt,
                                      int m, int b, int h, int w) {
    if (m == 0) return tgt[(b * HH + h) * WW + w] > 0;                 // gt mask
    return out[((b * 2 + 1) * HH + h) * WW + w] > 0.5f;                // seg mask
}

// Pass 1: vertical 1D distance, adaptive radius (exact equiv of BIG-init fw/bw
// scans). Writes g^2. Block 0 also zeroes the max accumulators.
__global__ void k_vert(const float* __restrict__ out, const int* __restrict__ tgt) {
    int idx = blockIdx.x * blockDim.x + threadIdx.x;   // [m][b][h][w]
    if (blockIdx.x == 0 && threadIdx.x < NGRP) g_maxbits[threadIdx.x] = 0u;

    int w = idx & (WW - 1);
    int h = (idx >> 9) & (HH - 1);
    int b = (idx >> 18) & (BB - 1);
    int m = idx >> 21;

    float g;
    if (!is_fg(out, tgt, m, b, h, w)) {
        g = 0.0f;
    } else {
        int r = 1, found = 0;
        while (true) {
            bool up = (h - r >= 0);
            bool dn = (h + r < HH);
            if (!up && !dn) break;
            if (up && !is_fg(out, tgt, m, b, h - r, w)) { found = 1; break; }
            if (dn && !is_fg(out, tgt, m, b, h + r, w)) { found = 1; break; }
            ++r;
        }
        g = found ? (float)r : (BIGF + (float)min(h + 1, HH - h));
    }
    g_dtsq[idx] = g * g;
}

// Pass 2: per-row exact lower-envelope min (adaptive window) in shared, then
// FUSED: read seg/gt rows, accumulate sum(d^2 * dt^2) per row + per-group max.
// dt^2 never goes back to HBM.
__global__ void k_horiz(const float* __restrict__ out, const int* __restrict__ tgt) {
    __shared__ float  s[WW];
    __shared__ float  smax[16];
    __shared__ double ssum[16];
    int row = blockIdx.x;                 // (m*BB + b)*HH + h
    int j = threadIdx.x;                  // 512 threads
    int m = row >> 12;                    // / (BB*HH)
    int b = (row >> 9) & (BB - 1);
    int h = row & (HH - 1);

    s[j] = g_dtsq[(size_t)row * WW + j];
    __syncthreads();

    float best = fminf(s[j], BIG2);       // matches reference best0 = BIG*BIG
    for (int r = 1; r < WW; ++r) {
        float rr = (float)(r * r);        // integer-exact in fp32
        if (rr >= best) break;            // rigorous cutoff: exactness preserved
        if (j >= r)      best = fminf(best, s[j - r] + rr);
        if (j + r < WW)  best = fminf(best, s[j + r] + rr);
    }

    // loss contribution of this pixel for mask m (unnormalized)
    float segv = out[((b * 2 + 1) * HH + h) * WW + j];
    float gtv  = (float)tgt[(b * HH + h) * WW + j];
    float d    = segv - gtv;
    double v   = (double)(d * d * best);
    float  mv  = best;

    // block reduce: sum (double) and max (float)
    #pragma unroll
    for (int o = 16; o > 0; o >>= 1) {
        v  += __shfl_xor_sync(0xffffffffu, v, o);
        mv  = fmaxf(mv, __shfl_xor_sync(0xffffffffu, mv, o));
    }
    if ((j & 31) == 0) { ssum[j >> 5] = v; smax[j >> 5] = mv; }
    __syncthreads();
    if (j < 32) {
        double x = (j < 16) ? ssum[j] : 0.0;
        float  y = (j < 16) ? smax[j] : 0.0f;
        #pragma unroll
        for (int o = 8; o > 0; o >>= 1) {
            x += __shfl_xor_sync(0xffffffffu, x, o);
            y  = fmaxf(y, __shfl_xor_sync(0xffffffffu, y, o));
        }
        if (j == 0) {
            g_rowsum[row] = x;
            atomicMax(&g_maxbits[(m << 3) | b], __float_as_uint(y));
        }
    }
}

// Pass 3: one block reduces 8192 row partials into the final scalar.
__global__ void k_finalize(float* __restrict__ o) {
    __shared__ double ssum[16];
    int t = threadIdx.x;                  // 512 threads
    double total = 0.0;
    for (int g = 0; g < NGRP; ++g) {
        double v = g_rowsum[g * HH + t];  // each group = 512 rows
        #pragma unroll
        for (int ofs = 16; ofs > 0; ofs >>= 1) v += __shfl_xor_sync(0xffffffffu, v, ofs);
        if ((t & 31) == 0) ssum[t >> 5] = v;
        __syncthreads();
        if (t == 0) {
            double s = 0.0;
            #pragma unroll
            for (int k = 0; k < 16; ++k) s += ssum[k];
            double mx = (double)fmaxf(__uint_as_float(g_maxbits[g]), 1.0f);
            total += s / mx;
        }
        __syncthreads();
    }
    if (t == 0) o[0] = (float)(total * (1.0 / (double)NPIX));
}

extern "C" void kernel_launch(void* const* d_in, const int* in_sizes, int n_in,
                              void* d_out, int out_size) {
    const float* out = (const float*)d_in[0];   // [8,2,512,512] float32
    const int*   tgt = (const int*)d_in[1];     // [8,1,512,512] int32

    k_vert<<<(NMASK * NPIX) / 256, 256>>>(out, tgt);
    k_horiz<<<NROWS, WW>>>(out, tgt);
    k_finalize<<<1, WW>>>((float*)d_out);
}

// round 3
// speedup vs baseline: 1.3249x; 1.3249x over previous
#include <cuda_runtime.h>

#define BB 8
#define HH 512
#define WW 512
#define NMASK 2
#define BIGF 1.0e6f
#define BIG2 1.0e12f
#define NPIX (BB * HH * WW)          // 2097152
#define NROWS (NMASK * BB * HH)      // 8192
#define NGRP  (NMASK * BB)           // 16
#define WPR   (WW / 32)              // 16 bit-words per row

// Packed fg bits: [m][b][h][w/32]  -> 2*8*512*16 words = 512 KB (L2-resident)
__device__ unsigned int g_bits[NMASK * BB * HH * WPR];
__device__ float        g_rowsum[NROWS];    // per-row unnormalized sum(d^2 * dt^2)
__device__ unsigned int g_maxbits[NGRP];    // per-(mask,batch) max dt^2 (float bits)

// Pass 1: pack fg masks into bits (and reset max accumulators each replay).
__global__ void k_bits(const float* __restrict__ out, const int* __restrict__ tgt) {
    int idx = blockIdx.x * blockDim.x + threadIdx.x;   // [m][b][h][w], w fastest
    if (blockIdx.x == 0 && threadIdx.x < NGRP) g_maxbits[threadIdx.x] = 0u;

    int w = idx & (WW - 1);
    int h = (idx >> 9) & (HH - 1);
    int b = (idx >> 18) & (BB - 1);
    int m = idx >> 21;

    bool fg = (m == 0) ? (tgt[(b * HH + h) * WW + w] > 0)
                       : (out[((b * 2 + 1) * HH + h) * WW + w] > 0.5f);
    unsigned ball = __ballot_sync(0xffffffffu, fg);
    if ((w & 31) == 0) g_bits[idx >> 5] = ball;
}

// Pass 2 (fused): per row — vertical 1D distance from bits (adaptive probe),
// exact horizontal lower-envelope in shared, loss contribution, fp32 row
// reduction + per-group max. No dt^2 ever touches HBM.
__global__ void k_main(const float* __restrict__ out) {
    __shared__ float s[WW];
    __shared__ float ssum[16];
    __shared__ float smax[16];

    int row = blockIdx.x;                 // (m*BB + b)*HH + h
    int j = threadIdx.x;                  // 512 threads
    int h  = row & (HH - 1);
    int mb = row >> 9;                    // m*BB + b
    int b  = mb & (BB - 1);

    const unsigned* rb = g_bits + (size_t)mb * HH * WPR + (j >> 5);
    unsigned bit = 1u << (j & 31);

    // ---- vertical distance (exact equiv of BIG-initialized fw/bw scans) ----
    float g;
    if (!(rb[h * WPR] & bit)) {
        g = 0.0f;
    } else {
        int r = 1, found = 0;
        while (true) {
            bool up = (h - r >= 0);
            bool dn = (h + r < HH);
            if (!up && !dn) break;
            if (up && !(rb[(h - r) * WPR] & bit)) { found = 1; break; }
            if (dn && !(rb[(h + r) * WPR] & bit)) { found = 1; break; }
            ++r;
        }
        g = found ? (float)r : (BIGF + (float)min(h + 1, HH - h));
    }
    s[j] = g * g;
    __syncthreads();

    // ---- horizontal exact envelope with rigorous adaptive cutoff ----
    float best = fminf(s[j], BIG2);       // matches reference best0 = BIG*BIG
    for (int r = 1; r < WW; ++r) {
        float rr = (float)(r * r);        // integer-exact in fp32
        if (rr >= best) break;            // gk + rr >= rr >= best: exact cutoff
        if (j >= r)      best = fminf(best, s[j - r] + rr);
        if (j + r < WW)  best = fminf(best, s[j + r] + rr);
    }

    // ---- loss contribution: gt float == gt bit (target in {0,1}) ----
    const unsigned* gtb = g_bits + (size_t)b * HH * WPR;   // m=0 section
    float gtv  = (gtb[h * WPR + (j >> 5)] & bit) ? 1.0f : 0.0f;
    float segv = out[((b * 2 + 1) * HH + h) * WW + j];
    float d    = segv - gtv;
    float v    = d * d * best;
    float mv   = best;

    // ---- fp32 block reduce (pairwise): sum + max ----
    #pragma unroll
    for (int o = 16; o > 0; o >>= 1) {
        v  += __shfl_xor_sync(0xffffffffu, v, o);
        mv  = fmaxf(mv, __shfl_xor_sync(0xffffffffu, mv, o));
    }
    if ((j & 31) == 0) { ssum[j >> 5] = v; smax[j >> 5] = mv; }
    __syncthreads();
    if (j < 32) {
        float x = (j < 16) ? ssum[j] : 0.0f;
        float y = (j < 16) ? smax[j] : 0.0f;
        #pragma unroll
        for (int o = 8; o > 0; o >>= 1) {
            x += __shfl_xor_sync(0xffffffffu, x, o);
            y  = fmaxf(y, __shfl_xor_sync(0xffffffffu, y, o));
        }
        if (j == 0) {
            g_rowsum[row] = x;
            atomicMax(&g_maxbits[mb], __float_as_uint(y));
        }
    }
}

// Pass 3: one block reduces 8192 fp32 row partials (double accumulation here only).
__global__ void k_finalize(float* __restrict__ o) {
    __shared__ double ssum[16];
    int t = threadIdx.x;                  // 512 threads
    double total = 0.0;
    for (int g = 0; g < NGRP; ++g) {
        double v = (double)g_rowsum[g * HH + t];   // each group = 512 rows
        #pragma unroll
        for (int ofs = 16; ofs > 0; ofs >>= 1) v += __shfl_xor_sync(0xffffffffu, v, ofs);
        if ((t & 31) == 0) ssum[t >> 5] = v;
        __syncthreads();
        if (t == 0) {
            double s = 0.0;
            #pragma unroll
            for (int k = 0; k < 16; ++k) s += ssum[k];
            double mx = (double)fmaxf(__uint_as_float(g_maxbits[g]), 1.0f);
            total += s / mx;
        }
        __syncthreads();
    }
    if (t == 0) o[0] = (float)(total * (1.0 / (double)NPIX));
}

extern "C" void kernel_launch(void* const* d_in, const int* in_sizes, int n_in,
                              void* d_out, int out_size) {
    const float* out = (const float*)d_in[0];   // [8,2,512,512] float32
    const int*   tgt = (const int*)d_in[1];     // [8,1,512,512] int32

    k_bits<<<(NMASK * NPIX) / 256, 256>>>(out, tgt);
    k_main<<<NROWS, WW>>>(out);
    k_finalize<<<1, WW>>>((float*)d_out);
}

// round 4
// speedup vs baseline: 1.7902x; 1.3513x over previous
#include <cuda_runtime.h>

#define BB 8
#define HH 512
#define WW 512
#define NMASK 2
#define BIGF 1.0e6f
#define BIG2 1.0e12f
#define NPIX (BB * HH * WW)          // 2097152
#define NROWS (NMASK * BB * HH)      // 8192
#define NGRP  (NMASK * BB)           // 16
#define KW    (HH / 32)              // 16 column-words per column

// Column-packed fg bits: [mb][k][w], bit (h&31) of word k=h>>5. 512 KB.
__device__ unsigned int g_cbits[NGRP * KW * WW];
__device__ float        g_rowsum[NROWS];
__device__ unsigned int g_maxbits[NGRP];

// Pass 1: pack masks into column words. Block = 256 threads handles a
// 32(h) x 256(w) tile; each thread builds one column word over 32
// coalesced row reads. No shared memory, no transpose.
__global__ void k_bits(const float* __restrict__ out, const int* __restrict__ tgt) {
    int bi = blockIdx.x;              // [mb][hc][wc]
    if (bi == 0 && threadIdx.x < NGRP) g_maxbits[threadIdx.x] = 0u;

    int wc = bi & 1;
    int hc = (bi >> 1) & (KW - 1);
    int mb = bi >> 5;
    int m = mb >> 3, b = mb & 7;
    int w = (wc << 8) + threadIdx.x;
    int h0 = hc << 5;

    unsigned word = 0;
    if (m == 0) {
        const int* p = tgt + ((size_t)(b * HH + h0)) * WW + w;
        #pragma unroll 8
        for (int hh = 0; hh < 32; ++hh)
            word |= (unsigned)(p[hh * WW] > 0) << hh;
    } else {
        const float* p = out + ((size_t)((b * 2 + 1) * HH + h0)) * WW + w;
        #pragma unroll 8
        for (int hh = 0; hh < 32; ++hh)
            word |= (unsigned)(p[hh * WW] > 0.5f) << hh;
    }
    g_cbits[(mb * KW + hc) * WW + w] = word;
}

// Pass 2 (fused): vertical distance via bit ops (O(1) typical), exact
// horizontal lower-envelope in shared, loss contribution, fp32 reduce.
__global__ void k_main(const float* __restrict__ out) {
    __shared__ float s[WW];
    __shared__ float ssum[16];
    __shared__ float smax[16];

    int row = blockIdx.x;             // (m*BB + b)*HH + h
    int j = threadIdx.x;              // 512 threads
    int h  = row & (HH - 1);
    int mb = row >> 9;
    int m  = mb >> 3, b = mb & 7;
    int k  = h >> 5;
    unsigned o = (unsigned)(h & 31);

    const unsigned* cb = g_cbits + (size_t)mb * KW * WW;
    unsigned c = cb[k * WW + j];      // coalesced: one word per thread

    float gval;
    if (!((c >> o) & 1u)) {
        gval = 0.0f;
    } else {
        // nearest background above (bit positions < o, then lower words)
        float u;
        unsigned inv = ~c & ((o == 0) ? 0u : ((1u << o) - 1u));
        if (inv) {
            u = (float)((int)o - (31 - __clz(inv)));
        } else {
            int kk = k - 1; unsigned iv = 0;
            while (kk >= 0 && !(iv = ~cb[kk * WW + j])) --kk;   // P~2^-32 per step
            u = (kk >= 0) ? (float)(h - (kk * 32 + 31 - __clz(iv)))
                          : (BIGF + (float)(h + 1));
        }
        // nearest background below (bit positions > o, then higher words)
        float dn;
        unsigned inv2 = ~c & (0xFFFFFFFEu << o);
        if (inv2) {
            dn = (float)((__ffs(inv2) - 1) - (int)o);
        } else {
            int kk = k + 1; unsigned iv = 0;
            while (kk < KW && !(iv = ~cb[kk * WW + j])) ++kk;
            dn = (kk < KW) ? (float)(kk * 32 + __ffs(iv) - 1 - h)
                           : (BIGF + (float)(HH - h));
        }
        gval = fminf(u, dn);
    }
    s[j] = gval * gval;
    __syncthreads();

    // exact horizontal envelope with rigorous adaptive cutoff
    float best = fminf(s[j], BIG2);   // matches reference best0 = BIG*BIG
    for (int r = 1; r < WW; ++r) {
        float rr = (float)(r * r);    // integer-exact in fp32
        if (rr >= best) break;        // gk + rr >= rr >= best: exact cutoff
        if (j >= r)      best = fminf(best, s[j - r] + rr);
        if (j + r < WW)  best = fminf(best, s[j + r] + rr);
    }

    // loss term: gt float == gt bit (target in {0,1}); gt word = m=0 section
    unsigned gtw = (m == 0) ? c : g_cbits[((size_t)b * KW + k) * WW + j];
    float gtv  = (float)((gtw >> o) & 1u);
    float segv = out[((size_t)((b * 2 + 1) * HH + h)) * WW + j];
    float d    = segv - gtv;
    float v    = d * d * best;
    float mv   = best;

    #pragma unroll
    for (int ofs = 16; ofs > 0; ofs >>= 1) {
        v  += __shfl_xor_sync(0xffffffffu, v, ofs);
        mv  = fmaxf(mv, __shfl_xor_sync(0xffffffffu, mv, ofs));
    }
    if ((j & 31) == 0) { ssum[j >> 5] = v; smax[j >> 5] = mv; }
    __syncthreads();
    if (j < 32) {
        float x = (j < 16) ? ssum[j] : 0.0f;
        float y = (j < 16) ? smax[j] : 0.0f;
        #pragma unroll
        for (int ofs = 8; ofs > 0; ofs >>= 1) {
            x += __shfl_xor_sync(0xffffffffu, x, ofs);
            y  = fmaxf(y, __shfl_xor_sync(0xffffffffu, y, ofs));
        }
        if (j == 0) {
            g_rowsum[row] = x;
            atomicMax(&g_maxbits[mb], __float_as_uint(y));
        }
    }
}

// Pass 3: one block reduces 8192 fp32 row partials (fp64 only here).
__global__ void k_finalize(float* __restrict__ o) {
    __shared__ double ssum[16];
    int t = threadIdx.x;              // 512 threads
    double total = 0.0;
    for (int g = 0; g < NGRP; ++g) {
        double v = (double)g_rowsum[g * HH + t];
        #pragma unroll
        for (int ofs = 16; ofs > 0; ofs >>= 1) v += __shfl_xor_sync(0xffffffffu, v, ofs);
        if ((t & 31) == 0) ssum[t >> 5] = v;
        __syncthreads();
        if (t == 0) {
            double sacc = 0.0;
            #pragma unroll
            for (int q = 0; q < 16; ++q) sacc += ssum[q];
            double mx = (double)fmaxf(__uint_as_float(g_maxbits[g]), 1.0f);
            total += sacc / mx;
        }
        __syncthreads();
    }
    if (t == 0) o[0] = (float)(total * (1.0 / (double)NPIX));
}

extern "C" void kernel_launch(void* const* d_in, const int* in_sizes, int n_in,
                              void* d_out, int out_size) {
    const float* out = (const float*)d_in[0];   // [8,2,512,512] float32
    const int*   tgt = (const int*)d_in[1];     // [8,1,512,512] int32

    k_bits<<<NGRP * KW * 2, 256>>>(out, tgt);   // 512 blocks
    k_main<<<NROWS, WW>>>(out);
    k_finalize<<<1, WW>>>((float*)d_out);
}

// round 5
// speedup vs baseline: 2.9235x; 1.6330x over previous
#include <cuda_runtime.h>

#define BB 8
#define HH 512
#define WW 512
#define NMASK 2
#define BIGF 1.0e6f
#define BIG2 1.0e12f
#define NPIX (BB * HH * WW)          // 2097152
#define NROWS (NMASK * BB * HH)      // 8192
#define NGRP  (NMASK * BB)           // 16
#define KW    (HH / 32)              // 16 column-words per column
#define PAD   4

// Column-packed fg bits: [mb][k][w], bit (h&31) of word k=h>>5. 512 KB.
__device__ unsigned int g_cbits[NGRP * KW * WW];
__device__ float        g_rowsum[NROWS];
__device__ unsigned int g_maxbits[NGRP];

// Pass 1: pack masks into column words. 512 threads per block handle a
// 32(h) x 256(w) tile; each thread gathers 16 rows (half word), shared OR.
__global__ void k_bits(const float* __restrict__ out, const int* __restrict__ tgt) {
    __shared__ unsigned sh[256];
    int bi = blockIdx.x;              // [mb][hc][wc]
    if (bi == 0 && threadIdx.x < NGRP) g_maxbits[threadIdx.x] = 0u;

    int wc = bi & 1;
    int hc = (bi >> 1) & (KW - 1);
    int mb = bi >> 5;
    int m = mb >> 3, b = mb & 7;
    int wl = threadIdx.x & 255;
    int half = threadIdx.x >> 8;      // 0: rows 0..15, 1: rows 16..31
    int w = (wc << 8) + wl;
    int h0 = (hc << 5) + (half << 4);

    unsigned word = 0;
    if (m == 0) {
        const int* p = tgt + ((size_t)(b * HH + h0)) * WW + w;
        #pragma unroll
        for (int hh = 0; hh < 16; ++hh)
            word |= (unsigned)(p[hh * WW] > 0) << ((half << 4) + hh);
    } else {
        const float* p = out + ((size_t)((b * 2 + 1) * HH + h0)) * WW + w;
        #pragma unroll
        for (int hh = 0; hh < 16; ++hh)
            word |= (unsigned)(p[hh * WW] > 0.5f) << ((half << 4) + hh);
    }
    if (half == 0) sh[wl] = word;
    __syncthreads();
    if (half == 1) g_cbits[(mb * KW + hc) * WW + w] = word | sh[wl];
}

// Pass 2 (fused): vertical distance via bit ops, exact horizontal envelope
// (straight-line r<=4 + exact early exit, rare fallback), loss, fp32 reduce.
__global__ void k_main(const float* __restrict__ out) {
    __shared__ float sp[PAD + WW + PAD];   // halo-padded row of g^2
    __shared__ float ssum[16];
    __shared__ float smax[16];

    int row = blockIdx.x;             // (m*BB + b)*HH + h
    int j = threadIdx.x;              // 512 threads
    int h  = row & (HH - 1);
    int mb = row >> 9;
    int m  = mb >> 3, b = mb & 7;
    int k  = h >> 5;
    unsigned o = (unsigned)(h & 31);

    const unsigned* cb = g_cbits + (size_t)mb * KW * WW;
    unsigned c = cb[k * WW + j];      // coalesced: one word per thread

    if (j < PAD) { sp[j] = BIG2; sp[PAD + WW + j] = BIG2; }

    float gval;
    if (!((c >> o) & 1u)) {
        gval = 0.0f;
    } else {
        // nearest background above (bit positions < o, then lower words)
        float u;
        unsigned inv = ~c & ((o == 0) ? 0u : ((1u << o) - 1u));
        if (inv) {
            u = (float)((int)o - (31 - __clz(inv)));
        } else {
            int kk = k - 1; unsigned iv = 0;
            while (kk >= 0 && !(iv = ~cb[kk * WW + j])) --kk;   // P~2^-32/step
            u = (kk >= 0) ? (float)(h - (kk * 32 + 31 - __clz(iv)))
                          : (BIGF + (float)(h + 1));
        }
        // nearest background below (bit positions > o, then higher words)
        float dn;
        unsigned inv2 = ~c & (0xFFFFFFFEu << o);
        if (inv2) {
            dn = (float)((__ffs(inv2) - 1) - (int)o);
        } else {
            int kk = k + 1; unsigned iv = 0;
            while (kk < KW && !(iv = ~cb[kk * WW + j])) ++kk;
            dn = (kk < KW) ? (float)(kk * 32 + __ffs(iv) - 1 - h)
                           : (BIGF + (float)(HH - h));
        }
        gval = fminf(u, dn);
    }
    sp[PAD + j] = gval * gval;
    __syncthreads();

    // exact horizontal envelope; straight-line r=1..4 with full ILP
    const float* sj = sp + PAD + j;
    float best = fminf(sj[0], BIG2);  // matches reference best0 = BIG*BIG
    float b1 = fminf(sj[-1] + 1.0f,  sj[1] + 1.0f);
    float b2 = fminf(sj[-2] + 4.0f,  sj[2] + 4.0f);
    float b3 = fminf(sj[-3] + 9.0f,  sj[3] + 9.0f);
    float b4 = fminf(sj[-4] + 16.0f, sj[4] + 16.0f);
    best = fminf(best, fminf(fminf(b1, b2), fminf(b3, b4)));
    if (best > 25.0f) {
        // fallback (needs a ~9-wide all-fg deep blob; p ~ 2^-54 per pixel)
        for (int r = 5; r < WW; ++r) {
            float rr = (float)(r * r);     // integer-exact in fp32
            if (rr >= best) break;         // rigorous exact cutoff
            if (j >= r)      best = fminf(best, sp[PAD + j - r] + rr);
            if (j + r < WW)  best = fminf(best, sp[PAD + j + r] + rr);
        }
    }

    // loss term: gt float == gt bit (target in {0,1}); gt word = m=0 section
    unsigned gtw = (m == 0) ? c : g_cbits[((size_t)b * KW + k) * WW + j];
    float gtv  = (float)((gtw >> o) & 1u);
    float segv = out[((size_t)((b * 2 + 1) * HH + h)) * WW + j];
    float d    = segv - gtv;
    float v    = d * d * best;
    float mv   = best;

    #pragma unroll
    for (int ofs = 16; ofs > 0; ofs >>= 1) {
        v  += __shfl_xor_sync(0xffffffffu, v, ofs);
        mv  = fmaxf(mv, __shfl_xor_sync(0xffffffffu, mv, ofs));
    }
    if ((j & 31) == 0) { ssum[j >> 5] = v; smax[j >> 5] = mv; }
    __syncthreads();
    if (j < 32) {
        float x = (j < 16) ? ssum[j] : 0.0f;
        float y = (j < 16) ? smax[j] : 0.0f;
        #pragma unroll
        for (int ofs = 8; ofs > 0; ofs >>= 1) {
            x += __shfl_xor_sync(0xffffffffu, x, ofs);
            y  = fmaxf(y, __shfl_xor_sync(0xffffffffu, y, ofs));
        }
        if (j == 0) {
            g_rowsum[row] = x;
            atomicMax(&g_maxbits[mb], __float_as_uint(y));
        }
    }
}

// Pass 3: 16 warps <-> 16 groups, one pass, deterministic double accumulation.
__global__ void k_finalize(float* __restrict__ o) {
    __shared__ double part[16];
    int t = threadIdx.x;              // 512 threads
    int g = t >> 5, l = t & 31;
    double acc = 0.0;
    #pragma unroll
    for (int i = 0; i < 16; ++i)
        acc += (double)g_rowsum[g * HH + i * 32 + l];
    #pragma unroll
    for (int ofs = 16; ofs > 0; ofs >>= 1)
        acc += __shfl_xor_sync(0xffffffffu, acc, ofs);
    if (l == 0) {
        double mx = (double)fmaxf(__uint_as_float(g_maxbits[g]), 1.0f);
        part[g] = acc / mx;
    }
    __syncthreads();
    if (t == 0) {
        double total = 0.0;
        #pragma unroll
        for (int q = 0; q < 16; ++q) total += part[q];
        o[0] = (float)(total * (1.0 / (double)NPIX));
    }
}

extern "C" void kernel_launch(void* const* d_in, const int* in_sizes, int n_in,
                              void* d_out, int out_size) {
    const float* out = (const float*)d_in[0];   // [8,2,512,512] float32
    const int*   tgt = (const int*)d_in[1];     // [8,1,512,512] int32

    k_bits<<<NGRP * KW * 2, 512>>>(out, tgt);   // 512 blocks x 512 thr
    k_main<<<NROWS, WW>>>(out);
    k_finalize<<<1, WW>>>((float*)d_out);
}

// round 6
// speedup vs baseline: 3.0553x; 1.0451x over previous
#include <cuda_runtime.h>

#define BB 8
#define HH 512
#define WW 512
#define NMASK 2
#define BIGF 1.0e6f
#define BIG2 1.0e12f
#define NPIX (BB * HH * WW)          // 2097152
#define NGRP  (NMASK * BB)           // 16
#define KW    (HH / 32)              // 16 column-words per column
#define PAD   4
#define MAIN_GRID (BB * HH)          // 4096 blocks, one per (b,h) row

// Column-packed fg bits: [mb][k][w], bit (h&31) of word k=h>>5. 512 KB.
__device__ unsigned int g_cbits[NGRP * KW * WW];
__device__ float        g_rowsum[NMASK][BB * HH];
__device__ unsigned int g_maxbits[NGRP];
__device__ unsigned int g_counter = 0;

// Pass 1: pack masks into column words, vec4 I/O. Block = 256 thr handles a
// 32(h) x 512(w) tile: 128 vec4 columns x 2 row-halves, shared OR combine.
__global__ void k_bits(const float* __restrict__ out, const int* __restrict__ tgt) {
    __shared__ uint4 sh[128];
    int bi = blockIdx.x;              // [mb][hc] : 16*16 = 256 blocks
    if (bi == 0 && threadIdx.x < NGRP) g_maxbits[threadIdx.x] = 0u;

    int hc = bi & (KW - 1);
    int mb = bi >> 4;
    int m = mb >> 3, b = mb & 7;
    int vw   = threadIdx.x & 127;     // vec4 column: w = vw*4
    int half = threadIdx.x >> 7;      // 0: rows 0..15, 1: rows 16..31
    int w  = vw << 2;
    int h0 = (hc << 5) + (half << 4);

    unsigned w0 = 0, w1 = 0, w2 = 0, w3 = 0;
    if (m == 0) {
        const int4* p = (const int4*)(tgt + (size_t)(b * HH + h0) * WW + w);
        #pragma unroll
        for (int hh = 0; hh < 16; ++hh) {
            int4 v = p[hh * (WW / 4)];
            unsigned s = (unsigned)((half << 4) + hh);
            w0 |= (unsigned)(v.x > 0) << s;
            w1 |= (unsigned)(v.y > 0) << s;
            w2 |= (unsigned)(v.z > 0) << s;
            w3 |= (unsigned)(v.w > 0) << s;
        }
    } else {
        const float4* p = (const float4*)(out + (size_t)((b * 2 + 1) * HH + h0) * WW + w);
        #pragma unroll
        for (int hh = 0; hh < 16; ++hh) {
            float4 v = p[hh * (WW / 4)];
            unsigned s = (unsigned)((half << 4) + hh);
            w0 |= (unsigned)(v.x > 0.5f) << s;
            w1 |= (unsigned)(v.y > 0.5f) << s;
            w2 |= (unsigned)(v.z > 0.5f) << s;
            w3 |= (unsigned)(v.w > 0.5f) << s;
        }
    }
    if (half == 0) sh[vw] = make_uint4(w0, w1, w2, w3);
    __syncthreads();
    if (half == 1) {
        uint4 o4 = sh[vw];
        ((uint4*)(g_cbits + (size_t)(mb * KW + hc) * WW))[vw] =
            make_uint4(w0 | o4.x, w1 | o4.y, w2 | o4.z, w3 | o4.w);
    }
}

// vertical 1D distance from column bits (exact equiv of BIG-init fw/bw scans)
__device__ __forceinline__ float vdist(const unsigned* __restrict__ cb, unsigned c,
                                       int h, int k, unsigned o, int j) {
    if (!((c >> o) & 1u)) return 0.0f;
    float u;
    unsigned inv = ~c & ((o == 0) ? 0u : ((1u << o) - 1u));
    if (inv) {
        u = (float)((int)o - (31 - __clz(inv)));
    } else {
        int kk = k - 1; unsigned iv = 0;
        while (kk >= 0 && !(iv = ~cb[kk * WW + j])) --kk;   // P~2^-32 per step
        u = (kk >= 0) ? (float)(h - (kk * 32 + 31 - __clz(iv)))
                      : (BIGF + (float)(h + 1));
    }
    float dn;
    unsigned inv2 = ~c & (0xFFFFFFFEu << o);
    if (inv2) {
        dn = (float)((__ffs(inv2) - 1) - (int)o);
    } else {
        int kk = k + 1; unsigned iv = 0;
        while (kk < KW && !(iv = ~cb[kk * WW + j])) ++kk;
        dn = (kk < KW) ? (float)(kk * 32 + __ffs(iv) - 1 - h)
                       : (BIGF + (float)(HH - h));
    }
    return fminf(u, dn);
}

// exact horizontal envelope: straight-line r<=4 (ILP) + exact early exit;
// fallback needs a ~9-wide all-fg deep blob (p ~ 2^-54 per pixel).
__device__ __forceinline__ float envelope(const float* __restrict__ sp, int j) {
    const float* sj = sp + PAD + j;
    float best = fminf(sj[0], BIG2);  // matches reference best0 = BIG*BIG
    float b1 = fminf(sj[-1] + 1.0f,  sj[1] + 1.0f);
    float b2 = fminf(sj[-2] + 4.0f,  sj[2] + 4.0f);
    float b3 = fminf(sj[-3] + 9.0f,  sj[3] + 9.0f);
    float b4 = fminf(sj[-4] + 16.0f, sj[4] + 16.0f);
    best = fminf(best, fminf(fminf(b1, b2), fminf(b3, b4)));
    if (best > 25.0f) {
        for (int r = 5; r < WW; ++r) {
            float rr = (float)(r * r);     // integer-exact in fp32
            if (rr >= best) break;         // rigorous exact cutoff
            if (j >= r)      best = fminf(best, sp[PAD + j - r] + rr);
            if (j + r < WW)  best = fminf(best, sp[PAD + j + r] + rr);
        }
    }
    return best;
}

// Pass 2: one block per (b,h) row computes BOTH masks; last block finalizes.
__global__ void k_main(const float* __restrict__ out, float* __restrict__ res) {
    __shared__ float sp0[PAD + WW + PAD];   // gt  g^2 row (halo-padded)
    __shared__ float sp1[PAD + WW + PAD];   // seg g^2 row
    __shared__ float red[4][16];
    __shared__ double part[16];
    __shared__ bool amLast;

    int row = blockIdx.x;             // b*HH + h
    int j = threadIdx.x;              // 512 threads
    int h = row & (HH - 1);
    int b = row >> 9;
    int k = h >> 5;
    unsigned o = (unsigned)(h & 31);

    const unsigned* cbg = g_cbits + (size_t)b * KW * WW;          // gt  (m=0)
    const unsigned* cbs = g_cbits + (size_t)(8 + b) * KW * WW;    // seg (m=1)
    unsigned cg = cbg[k * WW + j];
    unsigned cs = cbs[k * WW + j];

    if (j < PAD) {
        sp0[j] = BIG2; sp0[PAD + WW + j] = BIG2;
        sp1[j] = BIG2; sp1[PAD + WW + j] = BIG2;
    }
    float g0 = vdist(cbg, cg, h, k, o, j);
    float g1 = vdist(cbs, cs, h, k, o, j);
    sp0[PAD + j] = g0 * g0;
    sp1[PAD + j] = g1 * g1;
    __syncthreads();

    float best0 = envelope(sp0, j);
    float best1 = envelope(sp1, j);

    float gtv  = (float)((cg >> o) & 1u);   // gt float == gt bit
    float segv = out[((size_t)((b * 2 + 1) * HH + h)) * WW + j];
    float d  = segv - gtv;
    float d2 = d * d;
    float v0 = d2 * best0, v1 = d2 * best1;
    float m0 = best0,      m1 = best1;

    #pragma unroll
    for (int ofs = 16; ofs > 0; ofs >>= 1) {
        v0 += __shfl_xor_sync(0xffffffffu, v0, ofs);
        v1 += __shfl_xor_sync(0xffffffffu, v1, ofs);
        m0  = fmaxf(m0, __shfl_xor_sync(0xffffffffu, m0, ofs));
        m1  = fmaxf(m1, __shfl_xor_sync(0xffffffffu, m1, ofs));
    }
    if ((j & 31) == 0) {
        int wq = j >> 5;
        red[0][wq] = v0; red[1][wq] = v1; red[2][wq] = m0; red[3][wq] = m1;
    }
    __syncthreads();
    if (j < 32) {
        float x0 = (j < 16) ? red[0][j] : 0.0f;
        float x1 = (j < 16) ? red[1][j] : 0.0f;
        float y0 = (j < 16) ? red[2][j] : 0.0f;
        float y1 = (j < 16) ? red[3][j] : 0.0f;
        #pragma unroll
        for (int ofs = 8; ofs > 0; ofs >>= 1) {
            x0 += __shfl_xor_sync(0xffffffffu, x0, ofs);
            x1 += __shfl_xor_sync(0xffffffffu, x1, ofs);
            y0  = fmaxf(y0, __shfl_xor_sync(0xffffffffu, y0, ofs));
            y1  = fmaxf(y1, __shfl_xor_sync(0xffffffffu, y1, ofs));
        }
        if (j == 0) {
            g_rowsum[0][row] = x0;
            g_rowsum[1][row] = x1;
            atomicMax(&g_maxbits[b],     __float_as_uint(y0));
            atomicMax(&g_maxbits[8 + b], __float_as_uint(y1));
        }
    }

    // ---- last-block finalize (deterministic: all inputs fully written) ----
    __threadfence();
    if (j == 0) amLast = (atomicAdd(&g_counter, 1u) == MAIN_GRID - 1);
    __syncthreads();
    if (!amLast) return;

    int g = j >> 5, l = j & 31;       // 16 warps <-> 16 (mask,batch) groups
    int gm = g >> 3, gb = g & 7;
    double acc = 0.0;
    #pragma unroll
    for (int i = 0; i < 16; ++i)
        acc += (double)g_rowsum[gm][gb * HH + i * 32 + l];
    #pragma unroll
    for (int ofs = 16; ofs > 0; ofs >>= 1)
        acc += __shfl_xor_sync(0xffffffffu, acc, ofs);
    if (l == 0) {
        double mx = (double)fmaxf(__uint_as_float(g_maxbits[g]), 1.0f);
        part[g] = acc / mx;
    }
    __syncthreads();
    if (j == 0) {
        double total = 0.0;
        #pragma unroll
        for (int q = 0; q < 16; ++q) total += part[q];
        res[0] = (float)(total * (1.0 / (double)NPIX));
        g_counter = 0;                // reset for next replay
    }
}

extern "C" void kernel_launch(void* const* d_in, const int* in_sizes, int n_in,
                              void* d_out, int out_size) {
    const float* out = (const float*)d_in[0];   // [8,2,512,512] float32
    const int*   tgt = (const int*)d_in[1];     // [8,1,512,512] int32

    k_bits<<<NGRP * KW, 256>>>(out, tgt);       // 256 blocks
    k_main<<<MAIN_GRID, WW>>>(out, (float*)d_out);
}

// round 8
// speedup vs baseline: 3.9054x; 1.2783x over previous
#include <cuda_runtime.h>

#define BB 8
#define HH 512
#define WW 512
#define BIGF 1.0e6f
#define BIG2 1.0e12f
#define NPIX (BB * HH * WW)          // 2097152
#define NGRP  16
#define KW    (HH / 32)              // 16 column-words per column
#define PAD   4
#define RPB   4                      // rows per block
#define TPR   128                    // threads per row (4 px/thread)
#define MAIN_GRID (BB * HH / RPB)    // 1024

__device__ unsigned int g_cbits[NGRP * KW * WW];   // column-packed bits, 512 KB
__device__ float        g_rowsum[2][BB * HH];
__device__ unsigned int g_maxbits[NGRP];
__device__ unsigned int g_counter = 0;

// fp32 max over a warp via integer redux: exact for non-negative floats
// (IEEE bit pattern of non-negative floats is monotone in value).
__device__ __forceinline__ float redux_max_f32nn(float v) {
    unsigned r;
    asm("redux.sync.max.u32 %0, %1, 0xffffffff;" : "=r"(r) : "r"(__float_as_uint(v)));
    return __uint_as_float(r);
}

// Pass 1: pack masks into column words, vec4 I/O.
__global__ void k_bits(const float* __restrict__ out, const int* __restrict__ tgt) {
    __shared__ uint4 sh[128];
    int bi = blockIdx.x;              // [mb][hc] : 256 blocks
    if (bi == 0 && threadIdx.x < NGRP) g_maxbits[threadIdx.x] = 0u;

    int hc = bi & (KW - 1);
    int mb = bi >> 4;
    int m = mb >> 3, b = mb & 7;
    int vw   = threadIdx.x & 127;
    int half = threadIdx.x >> 7;
    int w  = vw << 2;
    int h0 = (hc << 5) + (half << 4);

    unsigned w0 = 0, w1 = 0, w2 = 0, w3 = 0;
    if (m == 0) {
        const int4* p = (const int4*)(tgt + (size_t)(b * HH + h0) * WW + w);
        #pragma unroll
        for (int hh = 0; hh < 16; ++hh) {
            int4 v = p[hh * (WW / 4)];
            unsigned s = (unsigned)((half << 4) + hh);
            w0 |= (unsigned)(v.x > 0) << s;  w1 |= (unsigned)(v.y > 0) << s;
            w2 |= (unsigned)(v.z > 0) << s;  w3 |= (unsigned)(v.w > 0) << s;
        }
    } else {
        const float4* p = (const float4*)(out + (size_t)((b * 2 + 1) * HH + h0) * WW + w);
        #pragma unroll
        for (int hh = 0; hh < 16; ++hh) {
            float4 v = p[hh * (WW / 4)];
            unsigned s = (unsigned)((half << 4) + hh);
            w0 |= (unsigned)(v.x > 0.5f) << s;  w1 |= (unsigned)(v.y > 0.5f) << s;
            w2 |= (unsigned)(v.z > 0.5f) << s;  w3 |= (unsigned)(v.w > 0.5f) << s;
        }
    }
    if (half == 0) sh[vw] = make_uint4(w0, w1, w2, w3);
    __syncthreads();
    if (half == 1) {
        uint4 o4 = sh[vw];
        ((uint4*)(g_cbits + (size_t)(mb * KW + hc) * WW))[vw] =
            make_uint4(w0 | o4.x, w1 | o4.y, w2 | o4.z, w3 | o4.w);
    }
}

// vertical 1D distance from column bits (exact equiv of BIG-init fw/bw scans)
__device__ __forceinline__ float vdist(const unsigned* __restrict__ cb, unsigned c,
                                       int h, int k, unsigned o, int j) {
    if (!((c >> o) & 1u)) return 0.0f;
    float u;
    unsigned inv = ~c & ((o == 0) ? 0u : ((1u << o) - 1u));
    if (inv) {
        u = (float)((int)o - (31 - __clz(inv)));
    } else {
        int kk = k - 1; unsigned iv = 0;
        while (kk >= 0 && !(iv = ~cb[kk * WW + j])) --kk;   // P~2^-32 per step
        u = (kk >= 0) ? (float)(h - (kk * 32 + 31 - __clz(iv)))
                      : (BIGF + (float)(h + 1));
    }
    float dn;
    unsigned inv2 = ~c & (0xFFFFFFFEu << o);
    if (inv2) {
        dn = (float)((__ffs(inv2) - 1) - (int)o);
    } else {
        int kk = k + 1; unsigned iv = 0;
        while (kk < KW && !(iv = ~cb[kk * WW + j])) ++kk;
        dn = (kk < KW) ? (float)(kk * 32 + __ffs(iv) - 1 - h)
                       : (BIGF + (float)(HH - h));
    }
    return fminf(u, dn);
}

// exact envelope for 4 consecutive pixels from a 12-value register window
// Wn[0..11] = s[w0-4 .. w0+7]; pixel i center at Wn[i+4].
__device__ __forceinline__ void env4(const float* Wn, const float* sprow,
                                     int w0, float* best) {
    #pragma unroll
    for (int i = 0; i < 4; ++i) {
        float bb = fminf(Wn[i + 4], BIG2);            // best0 = BIG*BIG clamp
        bb = fminf(bb, fminf(Wn[i + 3] + 1.0f,  Wn[i + 5] + 1.0f));
        bb = fminf(bb, fminf(Wn[i + 2] + 4.0f,  Wn[i + 6] + 4.0f));
        bb = fminf(bb, fminf(Wn[i + 1] + 9.0f,  Wn[i + 7] + 9.0f));
        bb = fminf(bb, fminf(Wn[i]     + 16.0f, Wn[i + 8] + 16.0f));
        if (bb > 25.0f) {   // fallback: needs ~9-wide all-fg blob, p ~ 2^-54
            int p = w0 + i;
            for (int r = 5; r < WW; ++r) {
                float rr = (float)(r * r);            // integer-exact in fp32
                if (rr >= bb) break;                  // rigorous exact cutoff
                if (p >= r)     bb = fminf(bb, sprow[PAD + p - r] + rr);
                if (p + r < WW) bb = fminf(bb, sprow[PAD + p + r] + rr);
            }
        }
        best[i] = bb;
    }
}

// Pass 2: block = 4 rows x 128 threads, 4 px/thread, both masks; last block
// performs the tiny finalize.
__global__ void __launch_bounds__(RPB * TPR)
k_main(const float* __restrict__ out, float* __restrict__ res) {
    __shared__ __align__(16) float sp[RPB][2][PAD + WW + PAD];
    __shared__ float red[RPB][4][TPR / 32];
    __shared__ double part[16];
    __shared__ bool amLast;

    int tid = threadIdx.x;
    int grp = tid >> 7;                     // row group 0..3
    int t   = tid & (TPR - 1);              // 0..127
    int b   = blockIdx.x >> 7;              // 128 blocks per batch
    int h   = ((blockIdx.x & 127) << 2) + grp;
    int row = (b << 9) + h;
    int k = h >> 5;
    unsigned o = (unsigned)(h & 31);
    int w0 = t << 2;

    const unsigned* cbg = g_cbits + (size_t)b * KW * WW;        // gt
    const unsigned* cbs = g_cbits + (size_t)(8 + b) * KW * WW;  // seg
    uint4 cg4 = *(const uint4*)(cbg + k * WW + w0);
    uint4 cs4 = *(const uint4*)(cbs + k * WW + w0);

    if (t < PAD) {
        sp[grp][0][t] = BIG2; sp[grp][0][PAD + WW + t] = BIG2;
        sp[grp][1][t] = BIG2; sp[grp][1][PAD + WW + t] = BIG2;
    }

    float c0[4], c1[4];
    {
        unsigned cw[4] = {cg4.x, cg4.y, cg4.z, cg4.w};
        #pragma unroll
        for (int i = 0; i < 4; ++i) { float g = vdist(cbg, cw[i], h, k, o, w0 + i); c0[i] = g * g; }
    }
    {
        unsigned cw[4] = {cs4.x, cs4.y, cs4.z, cs4.w};
        #pragma unroll
        for (int i = 0; i < 4; ++i) { float g = vdist(cbs, cw[i], h, k, o, w0 + i); c1[i] = g * g; }
    }
    *(float4*)&sp[grp][0][PAD + w0] = make_float4(c0[0], c0[1], c0[2], c0[3]);
    *(float4*)&sp[grp][1][PAD + w0] = make_float4(c1[0], c1[1], c1[2], c1[3]);
    __syncthreads();

    float b0[4], b1[4];
    {
        float4 L = *(const float4*)&sp[grp][0][w0];             // s[w0-4..w0-1]
        float4 R = *(const float4*)&sp[grp][0][PAD + w0 + 4];   // s[w0+4..w0+7]
        float Wn[12] = {L.x, L.y, L.z, L.w, c0[0], c0[1], c0[2], c0[3], R.x, R.y, R.z, R.w};
        env4(Wn, sp[grp][0], w0, b0);
    }
    {
        float4 L = *(const float4*)&sp[grp][1][w0];
        float4 R = *(const float4*)&sp[grp][1][PAD + w0 + 4];
        float Wn[12] = {L.x, L.y, L.z, L.w, c1[0], c1[1], c1[2], c1[3], R.x, R.y, R.z, R.w};
        env4(Wn, sp[grp][1], w0, b1);
    }

    // loss: gt float == gt bit (target in {0,1})
    float4 sv = *(const float4*)(out + ((size_t)((b * 2 + 1) * HH + h)) * WW + w0);
    float segv[4] = {sv.x, sv.y, sv.z, sv.w};
    unsigned cw[4] = {cg4.x, cg4.y, cg4.z, cg4.w};
    float v0 = 0.0f, v1 = 0.0f, m0 = 0.0f, m1 = 0.0f;
    #pragma unroll
    for (int i = 0; i < 4; ++i) {
        float gtv = (float)((cw[i] >> o) & 1u);
        float d = segv[i] - gtv;
        float d2 = d * d;
        v0 += d2 * b0[i];  v1 += d2 * b1[i];
        m0 = fmaxf(m0, b0[i]);  m1 = fmaxf(m1, b1[i]);
    }

    // warp reduce: sums via shfl butterfly, maxes via integer redux (1 instr)
    #pragma unroll
    for (int ofs = 16; ofs > 0; ofs >>= 1) {
        v0 += __shfl_xor_sync(0xffffffffu, v0, ofs);
        v1 += __shfl_xor_sync(0xffffffffu, v1, ofs);
    }
    m0 = redux_max_f32nn(m0);
    m1 = redux_max_f32nn(m1);
    int wq = t >> 5;
    if ((t & 31) == 0) {
        red[grp][0][wq] = v0; red[grp][1][wq] = v1;
        red[grp][2][wq] = m0; red[grp][3][wq] = m1;
    }
    __syncthreads();
    if (t == 0) {
        float x0 = (red[grp][0][0] + red[grp][0][1]) + (red[grp][0][2] + red[grp][0][3]);
        float x1 = (red[grp][1][0] + red[grp][1][1]) + (red[grp][1][2] + red[grp][1][3]);
        float y0 = fmaxf(fmaxf(red[grp][2][0], red[grp][2][1]), fmaxf(red[grp][2][2], red[grp][2][3]));
        float y1 = fmaxf(fmaxf(red[grp][3][0], red[grp][3][1]), fmaxf(red[grp][3][2], red[grp][3][3]));
        g_rowsum[0][row] = x0;
        g_rowsum[1][row] = x1;
        atomicMax(&g_maxbits[b],     __float_as_uint(y0));
        atomicMax(&g_maxbits[8 + b], __float_as_uint(y1));
    }

    // ---- last-block finalize (deterministic: all inputs fully written) ----
    __threadfence();
    if (tid == 0) amLast = (atomicAdd(&g_counter, 1u) == MAIN_GRID - 1);
    __syncthreads();
    if (!amLast) return;

    int g = tid >> 5, l = tid & 31;       // 16 warps <-> 16 (mask,batch) groups
    if (g < 16) {
        int gm = g >> 3, gb = g & 7;
        double acc = 0.0;
        #pragma unroll
        for (int i = 0; i < 16; ++i)
            acc += (double)g_rowsum[gm][gb * HH + i * 32 + l];
        #pragma unroll
        for (int ofs = 16; ofs > 0; ofs >>= 1)
            acc += __shfl_xor_sync(0xffffffffu, acc, ofs);
        if (l == 0) {
            double mx = (double)fmaxf(__uint_as_float(g_maxbits[g]), 1.0f);
            part[g] = acc / mx;
        }
    }
    __syncthreads();
    if (tid == 0) {
        double total = 0.0;
        #pragma unroll
        for (int q = 0; q < 16; ++q) total += part[q];
        res[0] = (float)(total * (1.0 / (double)NPIX));
        g_counter = 0;                    // reset for next replay
    }
}

extern "C" void kernel_launch(void* const* d_in, const int* in_sizes, int n_in,
                              void* d_out, int out_size) {
    const float* out = (const float*)d_in[0];   // [8,2,512,512] float32
    const int*   tgt = (const int*)d_in[1];     // [8,1,512,512] int32

    k_bits<<<NGRP * KW, 256>>>(out, tgt);       // 256 blocks
    k_main<<<MAIN_GRID, RPB * TPR>>>(out, (float*)d_out);
}